// round 11
// baseline (speedup 1.0000x reference)
#include <cuda_runtime.h>
#include <math.h>

// Problem constants: NS = NT = 80, D = 512, N = 6400, kdiag = 79*79 = 6241.
#define NSd   80
#define Dd    512
#define Nn    6400
#define GPERS 148   // persistent grid; launch_bounds(256,2) guarantees co-residency

// ---------------- device scratch (no allocation allowed) ----------------
__device__ float g_e1[NSd * Dd];
__device__ float g_e2[NSd * Dd];
__device__ float g_m1[NSd * Dd];
__device__ float g_m2[NSd * Dd];
__device__ float g_x1[NSd * Dd];
__device__ float g_x2[NSd * Dd];
__device__ float g_y1[NSd * Dd];
__device__ float g_y2[NSd * Dd];
__device__ float g_Mp0[NSd * NSd];
__device__ float g_v[Nn];           // v[p] = Mp[p%80, p/80]
__device__ float g_inv[64 * 64];    // invL of current diag block
__device__ int   g_cnt;             // grid barrier arrival counter
__device__ int   g_gen;             // grid barrier generation

__device__ __forceinline__ float warp_sum(float s) {
#pragma unroll
    for (int o = 16; o > 0; o >>= 1) s += __shfl_xor_sync(0xffffffffu, s, o);
    return s;
}

// ---------------- phase 1: small embedding chain (~25us total) ----------------

__global__ void k_transpose(const float* __restrict__ us, const float* __restrict__ ut) {
    int idx = blockIdx.x * blockDim.x + threadIdx.x;
    if (idx < NSd * Dd) {
        int i = idx >> 9, d = idx & 511;
        g_e1[idx] = us[d * NSd + i];
        g_e2[idx] = ut[d * NSd + i];
    }
}

__global__ void k_mp0(const float* __restrict__ iou) {
    int i = blockIdx.x;
    int warp = threadIdx.x >> 5, lane = threadIdx.x & 31;
    const float* a = g_e1 + i * Dd;
    for (int j = warp; j < NSd; j += 4) {
        const float* b = g_e2 + j * Dd;
        float s = 0.f;
#pragma unroll 4
        for (int d = lane; d < Dd; d += 32) s += a[d] * b[d];
        s = warp_sum(s);
        if (lane == 0) g_Mp0[i * NSd + j] = s + iou[i * NSd + j];
    }
}

__global__ void k_m1m2() {
    int r = blockIdx.x, which = blockIdx.y;
    __shared__ float w[NSd];
    int tid = threadIdx.x;
    if (tid < NSd) w[tid] = (which == 0) ? g_Mp0[r * NSd + tid] : g_Mp0[tid * NSd + r];
    __syncthreads();
    const float* E = (which == 0) ? g_e2 : g_e1;
    float* out     = (which == 0) ? g_m1 : g_m2;
    float acc = 0.f;
#pragma unroll 8
    for (int t = 0; t < NSd; t++) acc += w[t] * E[t * Dd + tid];
    out[r * Dd + tid] = acc;
}

__global__ void k_lamprep() {
    int r = blockIdx.x, which = blockIdx.y;
    const float* e = ((which == 0) ? g_e1 : g_e2) + r * Dd;
    const float* m = ((which == 0) ? g_m1 : g_m2) + r * Dd;
    float* x       = ((which == 0) ? g_x1 : g_x2) + r * Dd;
    float se = 0.f, sm = 0.f;
    for (int d = threadIdx.x; d < Dd; d += 256) {
        float ev = e[d], mv = m[d];
        se += ev * ev; sm += mv * mv;
    }
    se = warp_sum(se); sm = warp_sum(sm);
    __shared__ float rs[8], rm[8], lamS;
    int warp = threadIdx.x >> 5, lane = threadIdx.x & 31;
    if (lane == 0) { rs[warp] = se; rm[warp] = sm; }
    __syncthreads();
    if (threadIdx.x == 0) {
        float SE = 0.f, SM = 0.f;
        for (int t = 0; t < 8; t++) { SE += rs[t]; SM += rm[t]; }
        lamS = sqrtf(SE) / sqrtf(SM);
    }
    __syncthreads();
    float lam = lamS;
    for (int d = threadIdx.x; d < Dd; d += 256) x[d] = e[d] + lam * m[d];
}

__global__ void k_gemmW(const float* __restrict__ W, const float* __restrict__ b) {
    int i = blockIdx.x, which = blockIdx.y;
    const float* X = ((which == 0) ? g_x1 : g_x2) + i * Dd;
    float* Y       = ((which == 0) ? g_y1 : g_y2) + i * Dd;
    __shared__ float xs[Dd];
    for (int d = threadIdx.x; d < Dd; d += 128) xs[d] = X[d];
    __syncthreads();
    int warp = threadIdx.x >> 5, lane = threadIdx.x & 31;
    for (int o = warp; o < Dd; o += 4) {
        const float* wr = W + o * Dd;
        float s = 0.f;
#pragma unroll 4
        for (int d = lane; d < Dd; d += 32) s += xs[d] * wr[d];
        s = warp_sum(s);
        if (lane == 0) Y[o] = fmaxf(s + b[o], 0.f);
    }
}

__global__ void k_norm() {
    int r = blockIdx.x, which = blockIdx.y;
    float* y = ((which == 0) ? g_y1 : g_y2) + r * Dd;
    float s = 0.f;
    for (int d = threadIdx.x; d < Dd; d += 256) { float v = y[d]; s += v * v; }
    s = warp_sum(s);
    __shared__ float rs[8]; __shared__ float invS;
    int warp = threadIdx.x >> 5, lane = threadIdx.x & 31;
    if (lane == 0) rs[warp] = s;
    __syncthreads();
    if (threadIdx.x == 0) {
        float S = 0.f;
        for (int t = 0; t < 8; t++) S += rs[t];
        invS = 1.0f / fmaxf(sqrtf(S), 1e-12f);
    }
    __syncthreads();
    float inv = invS;
    for (int d = threadIdx.x; d < Dd; d += 256) y[d] *= inv;
}

__global__ void k_mp_thr(float* __restrict__ Mp_out, float* __restrict__ flag_out,
                         const float* __restrict__ kf, const float* __restrict__ iou,
                         const float* __restrict__ thrp) {
    int i = blockIdx.x;
    int warp = threadIdx.x >> 5, lane = threadIdx.x & 31;
    const float* a = g_y1 + i * Dd;
    float th = thrp[0];
    for (int j = warp; j < NSd; j += 4) {
        const float* b = g_y2 + j * Dd;
        float s = 0.f;
#pragma unroll 4
        for (int d = lane; d < Dd; d += 32) s += a[d] * b[d];
        s = warp_sum(s);
        if (lane == 0) {
            Mp_out[i * NSd + j] = s;
            g_v[j * NSd + i] = s;
            float fl = (kf[i * NSd + j] == -1.0f || iou[i * NSd + j] == 0.0f || s < th) ? 1.0f : 0.0f;
            flag_out[i * NSd + j] = fl;
        }
    }
}

// ---------------- phase 2: build A into the L output region; reset barrier ----------------
__global__ void k_buildA(float* __restrict__ L) {
    if (blockIdx.x == 0 && threadIdx.x == 0) { g_cnt = 0; g_gen = 0; }
    int p = blockIdx.x;
    int s1 = p % NSd, t1 = p / NSd;
    float vp = g_v[p];
    float* row = L + (size_t)p * Nn;
    for (int q = threadIdx.x; q < Nn; q += 256) {
        float val = 0.f;
        if (q == p) val = 6241.0f;
        else if (q < p) {
            int s2 = q % NSd, t2 = q / NSd;
            if (s1 != s2 && t1 != t2) val = -0.5f * (vp + g_v[q]);
        }
        row[q] = val;
    }
}

// ---------------- phase 3: persistent two-level Cholesky (outer 256, inner 64) ----------

__device__ __forceinline__ void grid_sync() {
    __threadfence();
    __syncthreads();
    if (threadIdx.x == 0) {
        int gen = atomicAdd(&g_gen, 0);
        if (atomicAdd(&g_cnt, 1) == (int)gridDim.x - 1) {
            g_cnt = 0;
            __threadfence();
            atomicExch(&g_gen, gen + 1);
        } else {
            while (atomicAdd(&g_gen, 0) == gen) { }
        }
    }
    __syncthreads();
}

// Factor 64x64 block at A (ld = Nn) in place (lower); write invL into g_inv.
__device__ void fact64(float* __restrict__ A, float* __restrict__ sbuf) {
    float* Lsh    = sbuf;            // 64*65
    float* colbuf = sbuf + 64 * 65;  // 64
    int tid = threadIdx.x;

    for (int idx = tid; idx < 64 * 64; idx += 256) {
        int r = idx >> 6, c = idx & 63;
        if (c <= r) Lsh[r * 65 + c] = A[(size_t)r * Nn + c];
    }
    __syncthreads();

    int tq = tid & 63, trow = tid >> 6;
    for (int c = 0; c < 64; c++) {
        if (tid < 64) colbuf[tid] = Lsh[tid * 65 + c];
        __syncthreads();
        float dv  = sqrtf(colbuf[c]);
        float inv = 1.0f / dv;
        float i2  = inv * inv;
        if (tid < 64) {
            if (tid > c)       Lsh[tid * 65 + c] = colbuf[tid] * inv;
            else if (tid == c) Lsh[c * 65 + c]   = dv;
        }
        if (tq > c) {
            float xq = colbuf[tq] * i2;
            for (int rr = c + 1 + trow; rr < 64; rr += 4)
                Lsh[rr * 65 + tq] -= colbuf[rr] * xq;
        }
        __syncthreads();
    }

    for (int idx = tid; idx < 64 * 64; idx += 256) {
        int r = idx >> 6, c = idx & 63;
        if (c <= r) A[(size_t)r * Nn + c] = Lsh[r * 65 + c];
    }

    if (tid < 64) colbuf[tid] = 1.0f / Lsh[tid * 65 + tid];
    __syncthreads();

    if (tid < 64) {
        int c = tid;
        float x[64];
        x[c] = colbuf[c];
        for (int jj = c + 1; jj < 64; jj++) {
            float s0 = 0.f, s1 = 0.f, s2 = 0.f, s3 = 0.f;
            int k = c;
            for (; k + 3 < jj; k += 4) {
                s0 += Lsh[jj * 65 + k + 0] * x[k + 0];
                s1 += Lsh[jj * 65 + k + 1] * x[k + 1];
                s2 += Lsh[jj * 65 + k + 2] * x[k + 2];
                s3 += Lsh[jj * 65 + k + 3] * x[k + 3];
            }
            for (; k < jj; k++) s0 += Lsh[jj * 65 + k] * x[k];
            x[jj] = -((s0 + s1) + (s2 + s3)) * colbuf[jj];
        }
        for (int jj = 0; jj < 64; jj++)
            g_inv[jj * 64 + c] = (jj >= c) ? x[jj] : 0.f;
    }
    __syncthreads();
}

// Panel solve tile: X = B * invL^T for 128 rows at row0 (in place), step j.
__device__ void trsm_tile(float* __restrict__ L, int j, int M, int row0,
                          float* __restrict__ sbuf) {
    float (*As)[132] = (float(*)[132])sbuf;
    float (*Bs)[68]  = (float(*)[68])(sbuf + 16 * 132);
    float* B = L + (size_t)(j + 64) * Nn + j;
    int tid = threadIdx.x;
    float acc[4][8];
#pragma unroll
    for (int u = 0; u < 4; u++)
#pragma unroll
        for (int v = 0; v < 8; v++) acc[u][v] = 0.f;

    int ty = tid >> 3, tx = tid & 7;
    int rr = ty * 4, cc = tx * 8;

    int li[2], lk4[2];
#pragma unroll
    for (int rep = 0; rep < 2; rep++) {
        int f4 = tid + rep * 256;
        li[rep]  = f4 >> 2;
        lk4[rep] = (f4 & 3) << 2;
    }
    int ci  = tid >> 2;
    int ck4 = (tid & 3) << 2;

    float4 pa[2], pbv;
#pragma unroll
    for (int rep = 0; rep < 2; rep++) {
        pa[rep] = make_float4(0.f, 0.f, 0.f, 0.f);
        if (row0 + li[rep] < M)
            pa[rep] = *(const float4*)(B + (size_t)(row0 + li[rep]) * Nn + lk4[rep]);
    }
    pbv = *(const float4*)(g_inv + ci * 64 + ck4);

    for (int kk = 0; kk < 64; kk += 16) {
        __syncthreads();
#pragma unroll
        for (int rep = 0; rep < 2; rep++) {
            As[lk4[rep] + 0][li[rep]] = pa[rep].x;
            As[lk4[rep] + 1][li[rep]] = pa[rep].y;
            As[lk4[rep] + 2][li[rep]] = pa[rep].z;
            As[lk4[rep] + 3][li[rep]] = pa[rep].w;
        }
        Bs[ck4 + 0][ci] = pbv.x; Bs[ck4 + 1][ci] = pbv.y;
        Bs[ck4 + 2][ci] = pbv.z; Bs[ck4 + 3][ci] = pbv.w;
        __syncthreads();
        if (kk < 48) {
            int nk = kk + 16;
#pragma unroll
            for (int rep = 0; rep < 2; rep++) {
                pa[rep] = make_float4(0.f, 0.f, 0.f, 0.f);
                if (row0 + li[rep] < M)
                    pa[rep] = *(const float4*)(B + (size_t)(row0 + li[rep]) * Nn + nk + lk4[rep]);
            }
            pbv = *(const float4*)(g_inv + ci * 64 + nk + ck4);
        }
#pragma unroll
        for (int k = 0; k < 16; k++) {
            float a[4], bq[8];
            *(float4*)&a[0]  = *(const float4*)&As[k][rr];
            *(float4*)&bq[0] = *(const float4*)&Bs[k][cc];
            *(float4*)&bq[4] = *(const float4*)&Bs[k][cc + 4];
#pragma unroll
            for (int u = 0; u < 4; u++)
#pragma unroll
                for (int v = 0; v < 8; v++) acc[u][v] += a[u] * bq[v];
        }
    }
    __syncthreads();
#pragma unroll
    for (int u = 0; u < 4; u++) {
        int gr = row0 + rr + u;
        if (gr < M) {
            float* bp = B + (size_t)gr * Nn + cc;
            float4 c0, c1;
            c0.x = acc[u][0]; c0.y = acc[u][1]; c0.z = acc[u][2]; c0.w = acc[u][3];
            c1.x = acc[u][4]; c1.y = acc[u][5]; c1.z = acc[u][6]; c1.w = acc[u][7];
            *(float4*)bp = c0;
            *(float4*)(bp + 4) = c1;
        }
    }
}

// Inner panel update tile: 128 rows x 64 cols, K=64.
// L[gr, gc] -= sum_k P[gr,k]*P[gc,k],  P = solved col block j.
__device__ void gemm_inner_tile(float* __restrict__ L, int j, int M, int row0, int C0,
                                float* __restrict__ sbuf) {
    float (*As)[132] = (float(*)[132])sbuf;
    float (*Bs)[68]  = (float(*)[68])(sbuf + 16 * 132);
    float* P = L + (size_t)(j + 64) * Nn + j;      // rows relative to j+64
    const float* Bg = L + (size_t)C0 * Nn + j;     // panel rows C0..C0+64
    int tid = threadIdx.x;
    float acc[4][8];
#pragma unroll
    for (int u = 0; u < 4; u++)
#pragma unroll
        for (int v = 0; v < 8; v++) acc[u][v] = 0.f;

    int ty = tid >> 3, tx = tid & 7;
    int rr = ty * 4, cc = tx * 8;

    int li[2], lk4[2];
#pragma unroll
    for (int rep = 0; rep < 2; rep++) {
        int f4 = tid + rep * 256;
        li[rep]  = f4 >> 2;
        lk4[rep] = (f4 & 3) << 2;
    }
    int ci  = tid >> 2;
    int ck4 = (tid & 3) << 2;

    float4 pa[2], pbv;
#pragma unroll
    for (int rep = 0; rep < 2; rep++) {
        pa[rep] = make_float4(0.f, 0.f, 0.f, 0.f);
        if (row0 + li[rep] < M)
            pa[rep] = *(const float4*)(P + (size_t)(row0 + li[rep]) * Nn + lk4[rep]);
    }
    pbv = *(const float4*)(Bg + (size_t)ci * Nn + ck4);

    for (int kk = 0; kk < 64; kk += 16) {
        __syncthreads();
#pragma unroll
        for (int rep = 0; rep < 2; rep++) {
            As[lk4[rep] + 0][li[rep]] = pa[rep].x;
            As[lk4[rep] + 1][li[rep]] = pa[rep].y;
            As[lk4[rep] + 2][li[rep]] = pa[rep].z;
            As[lk4[rep] + 3][li[rep]] = pa[rep].w;
        }
        Bs[ck4 + 0][ci] = pbv.x; Bs[ck4 + 1][ci] = pbv.y;
        Bs[ck4 + 2][ci] = pbv.z; Bs[ck4 + 3][ci] = pbv.w;
        __syncthreads();
        if (kk < 48) {
            int nk = kk + 16;
#pragma unroll
            for (int rep = 0; rep < 2; rep++) {
                pa[rep] = make_float4(0.f, 0.f, 0.f, 0.f);
                if (row0 + li[rep] < M)
                    pa[rep] = *(const float4*)(P + (size_t)(row0 + li[rep]) * Nn + nk + lk4[rep]);
            }
            pbv = *(const float4*)(Bg + (size_t)ci * Nn + nk + ck4);
        }
#pragma unroll
        for (int k = 0; k < 16; k++) {
            float a[4], bq[8];
            *(float4*)&a[0]  = *(const float4*)&As[k][rr];
            *(float4*)&bq[0] = *(const float4*)&Bs[k][cc];
            *(float4*)&bq[4] = *(const float4*)&Bs[k][cc + 4];
#pragma unroll
            for (int u = 0; u < 4; u++)
#pragma unroll
                for (int v = 0; v < 8; v++) acc[u][v] += a[u] * bq[v];
        }
    }
    __syncthreads();

    int R0g = j + 64 + row0;
    if (R0g >= C0 + 64) {
#pragma unroll
        for (int u = 0; u < 4; u++) {
            int gr = R0g + rr + u;
            if (gr < Nn) {
                float* cp = L + (size_t)gr * Nn + C0 + cc;
                float4 c0 = *(float4*)cp;
                float4 c1 = *(float4*)(cp + 4);
                c0.x -= acc[u][0]; c0.y -= acc[u][1]; c0.z -= acc[u][2]; c0.w -= acc[u][3];
                c1.x -= acc[u][4]; c1.y -= acc[u][5]; c1.z -= acc[u][6]; c1.w -= acc[u][7];
                *(float4*)cp = c0;
                *(float4*)(cp + 4) = c1;
            }
        }
    } else {
#pragma unroll
        for (int u = 0; u < 4; u++) {
            int gr = R0g + rr + u;
            if (gr < Nn) {
#pragma unroll
                for (int v = 0; v < 8; v++) {
                    int gc = C0 + cc + v;
                    if (gc <= gr) L[(size_t)gr * Nn + gc] -= acc[u][v];
                }
            }
        }
    }
}

// Trailing-update tile, K=256: C(128x128 at by,bx) -= P*P^T, P = M x 256 solved panel.
__device__ void syrk256_tile(float* __restrict__ L, int jo, int M, int bx, int by,
                             float* __restrict__ sbuf) {
    float (*As)[132] = (float(*)[132])sbuf;
    float (*Bs)[132] = (float(*)[132])(sbuf + 16 * 132);
    const float* P = L + (size_t)(jo + 256) * Nn + jo;
    float* C       = L + (size_t)(jo + 256) * Nn + (jo + 256);
    int row0 = by * 128, col0 = bx * 128;
    int tid = threadIdx.x;
    float acc[8][8];
#pragma unroll
    for (int u = 0; u < 8; u++)
#pragma unroll
        for (int v = 0; v < 8; v++) acc[u][v] = 0.f;

    int ty = tid >> 4, tx = tid & 15;
    int rr = ty * 8, cc = tx * 8;

    int li[2], lk4[2];
#pragma unroll
    for (int rep = 0; rep < 2; rep++) {
        int f4 = tid + rep * 256;
        li[rep]  = f4 >> 2;
        lk4[rep] = (f4 & 3) << 2;
    }

    float4 pa[2], pb[2];
#pragma unroll
    for (int rep = 0; rep < 2; rep++) {
        pa[rep] = make_float4(0.f, 0.f, 0.f, 0.f);
        pb[rep] = make_float4(0.f, 0.f, 0.f, 0.f);
        if (row0 + li[rep] < M)
            pa[rep] = *(const float4*)(P + (size_t)(row0 + li[rep]) * Nn + lk4[rep]);
        if (col0 + li[rep] < M)
            pb[rep] = *(const float4*)(P + (size_t)(col0 + li[rep]) * Nn + lk4[rep]);
    }

    for (int kk = 0; kk < 256; kk += 16) {
        __syncthreads();
#pragma unroll
        for (int rep = 0; rep < 2; rep++) {
            As[lk4[rep] + 0][li[rep]] = pa[rep].x;
            As[lk4[rep] + 1][li[rep]] = pa[rep].y;
            As[lk4[rep] + 2][li[rep]] = pa[rep].z;
            As[lk4[rep] + 3][li[rep]] = pa[rep].w;
            Bs[lk4[rep] + 0][li[rep]] = pb[rep].x;
            Bs[lk4[rep] + 1][li[rep]] = pb[rep].y;
            Bs[lk4[rep] + 2][li[rep]] = pb[rep].z;
            Bs[lk4[rep] + 3][li[rep]] = pb[rep].w;
        }
        __syncthreads();
        if (kk < 240) {
            int nk = kk + 16;
#pragma unroll
            for (int rep = 0; rep < 2; rep++) {
                pa[rep] = make_float4(0.f, 0.f, 0.f, 0.f);
                pb[rep] = make_float4(0.f, 0.f, 0.f, 0.f);
                if (row0 + li[rep] < M)
                    pa[rep] = *(const float4*)(P + (size_t)(row0 + li[rep]) * Nn + nk + lk4[rep]);
                if (col0 + li[rep] < M)
                    pb[rep] = *(const float4*)(P + (size_t)(col0 + li[rep]) * Nn + nk + lk4[rep]);
            }
        }
#pragma unroll
        for (int k = 0; k < 16; k++) {
            float a[8], bq[8];
            *(float4*)&a[0]  = *(const float4*)&As[k][rr];
            *(float4*)&a[4]  = *(const float4*)&As[k][rr + 4];
            *(float4*)&bq[0] = *(const float4*)&Bs[k][cc];
            *(float4*)&bq[4] = *(const float4*)&Bs[k][cc + 4];
#pragma unroll
            for (int u = 0; u < 8; u++)
#pragma unroll
                for (int v = 0; v < 8; v++) acc[u][v] += a[u] * bq[v];
        }
    }
    __syncthreads();

    if (by > bx) {
#pragma unroll
        for (int u = 0; u < 8; u++) {
            int gr = row0 + rr + u;
            if (gr < M) {
                float* cp = C + (size_t)gr * Nn + col0 + cc;
                float4 c0 = *(float4*)cp;
                float4 c1 = *(float4*)(cp + 4);
                c0.x -= acc[u][0]; c0.y -= acc[u][1]; c0.z -= acc[u][2]; c0.w -= acc[u][3];
                c1.x -= acc[u][4]; c1.y -= acc[u][5]; c1.z -= acc[u][6]; c1.w -= acc[u][7];
                *(float4*)cp = c0;
                *(float4*)(cp + 4) = c1;
            }
        }
    } else {
#pragma unroll
        for (int u = 0; u < 8; u++) {
            int gr = row0 + rr + u;
            if (gr < M) {
#pragma unroll
                for (int v = 0; v < 8; v++) {
                    int gc = col0 + cc + v;
                    if (gc <= gr) C[(size_t)gr * Nn + gc] -= acc[u][v];
                }
            }
        }
    }
}

// map s (0-based) to lower-triangle tile (bx <= by): s = by(by+1)/2 + bx
__device__ __forceinline__ void tri_xy(int s, int& bx, int& by) {
    int byp = (int)((sqrtf(8.0f * (float)s + 1.0f) - 1.0f) * 0.5f);
    while ((byp + 1) * (byp + 2) / 2 <= s) byp++;
    while (byp * (byp + 1) / 2 > s) byp--;
    by = byp;
    bx = s - ((byp * (byp + 1)) >> 1);
}

// Persistent two-level blocked Cholesky: outer 256, inner 64.
__global__ __launch_bounds__(256, 2) void chol_persist(float* __restrict__ L) {
    __shared__ float sbuf[4224];
    int bid = blockIdx.x;
    int G   = gridDim.x;

    if (bid == 0) fact64(L, sbuf);     // fact64(0)
    grid_sync();

    for (int jo = 0; jo < Nn; jo += 256) {
        for (int ji = 0; ji < 4; ji++) {
            int j  = jo + ji * 64;
            int M  = Nn - j - 64;                 // rows below diag block j
            int nt = M > 0 ? ((M + 127) >> 7) : 0;

            // ---- Phase A: full-height trsm of col block j ----
            for (int t = bid; t < nt; t += G)
                trsm_tile(L, j, M, t << 7, sbuf);
            grid_sync();

            // ---- Phase B: inner update of remaining panel cols + fact64(j+64) ----
            int w = (jo + 256) - (j + 64);        // 192,128,64,0
            if (w > 0) {
                int wu   = w >> 6;
                int ntot = nt * wu;               // tiles (t,u): r0 = t*128, C0 = j+64+u*64
                if (bid == 0) {
                    gemm_inner_tile(L, j, M, 0, j + 64, sbuf);   // tile (0,0) incl. diag
                    __syncthreads();
                    fact64(L + (size_t)(j + 64) * Nn + (j + 64), sbuf);
                } else {
                    for (int s = bid; s < ntot; s += G - 1) {
                        int t = s / wu, u = s - t * wu;
                        gemm_inner_tile(L, j, M, t << 7, j + 64 + (u << 6), sbuf);
                    }
                }
                grid_sync();
            }
        }

        // ---- Trailing update: C -= P*P^T with K = 256; fused fact64(jo+256) ----
        int Mt = Nn - jo - 256;
        if (Mt > 0) {
            int nt2 = (Mt + 127) >> 7;
            int ntS = nt2 * (nt2 + 1) / 2;
            if (bid == 0) {
                syrk256_tile(L, jo, Mt, 0, 0, sbuf);
                __syncthreads();
                fact64(L + (size_t)(jo + 256) * Nn + (jo + 256), sbuf);
            } else {
                for (int s = bid; s < ntS; s += G - 1) {   // s >= 1 skips tile (0,0)
                    int bx, by;
                    tri_xy(s, bx, by);
                    syrk256_tile(L, jo, Mt, bx, by, sbuf);
                }
            }
            grid_sync();
        }
    }
}

// ---------------- launch ----------------
extern "C" void kernel_launch(void* const* d_in, const int* in_sizes, int n_in,
                              void* d_out, int out_size) {
    (void)in_sizes; (void)n_in; (void)out_size;
    const float* U_src = (const float*)d_in[0];
    const float* U_tgt = (const float*)d_in[1];
    const float* kf    = (const float*)d_in[2];
    const float* thrp  = (const float*)d_in[3];
    const float* iou   = (const float*)d_in[4];
    const float* W     = (const float*)d_in[5];
    const float* b     = (const float*)d_in[6];

    float* out      = (float*)d_out;
    float* Mp_out   = out;                       // [80*80]
    float* Lm       = out + NSd * NSd;           // [6400*6400]
    float* flag_out = out + NSd * NSd + Nn * Nn; // [80*80]

    k_transpose<<<(NSd * Dd + 255) / 256, 256>>>(U_src, U_tgt);
    k_mp0<<<NSd, 128>>>(iou);
    k_m1m2<<<dim3(NSd, 2), 512>>>();
    k_lamprep<<<dim3(NSd, 2), 256>>>();
    k_gemmW<<<dim3(NSd, 2), 128>>>(W, b);
    k_norm<<<dim3(NSd, 2), 256>>>();
    k_mp_thr<<<NSd, 128>>>(Mp_out, flag_out, kf, iou, thrp);
    k_buildA<<<Nn, 256>>>(Lm);          // also resets the grid barrier

    chol_persist<<<GPERS, 256>>>(Lm);   // the entire Cholesky, one launch
}

// round 13
// speedup vs baseline: 1.1364x; 1.1364x over previous
#include <cuda_runtime.h>
#include <math.h>

// Problem constants: NS = NT = 80, D = 512, N = 6400, kdiag = 79*79 = 6241.
#define NSd   80
#define Dd    512
#define Nn    6400
#define GPERS 148   // persistent grid; launch_bounds(256,2) guarantees co-residency

// ---------------- device scratch (no allocation allowed) ----------------
__device__ float g_e1[NSd * Dd];
__device__ float g_e2[NSd * Dd];
__device__ float g_m1[NSd * Dd];
__device__ float g_m2[NSd * Dd];
__device__ float g_x1[NSd * Dd];
__device__ float g_x2[NSd * Dd];
__device__ float g_y1[NSd * Dd];
__device__ float g_y2[NSd * Dd];
__device__ float g_Mp0[NSd * NSd];
__device__ float g_v[Nn];             // v[p] = Mp[p%80, p/80]
__device__ float g_inv[64 * 64];      // invL of current diag block
__device__ int   g_cnt = 0;           // grid barrier arrival counter (self-restoring)
__device__ int   g_gen = 0;           // grid barrier generation (monotonic; compared relatively)

__device__ __forceinline__ float warp_sum(float s) {
#pragma unroll
    for (int o = 16; o > 0; o >>= 1) s += __shfl_xor_sync(0xffffffffu, s, o);
    return s;
}

__device__ __forceinline__ void grid_sync() {
    __threadfence();
    __syncthreads();
    if (threadIdx.x == 0) {
        int gen = atomicAdd(&g_gen, 0);
        if (atomicAdd(&g_cnt, 1) == (int)gridDim.x - 1) {
            g_cnt = 0;
            __threadfence();
            atomicExch(&g_gen, gen + 1);
        } else {
            while (atomicAdd(&g_gen, 0) == gen) { }
        }
    }
    __syncthreads();
}

// ---------------- Cholesky building blocks ----------------

// Factor 64x64 block at A (ld = Nn) in place (lower); write invL into g_inv.
__device__ void fact64(float* __restrict__ A, float* __restrict__ sbuf) {
    float* Lsh    = sbuf;            // 64*65
    float* colbuf = sbuf + 64 * 65;  // 64
    int tid = threadIdx.x;

    for (int idx = tid; idx < 64 * 64; idx += 256) {
        int r = idx >> 6, c = idx & 63;
        if (c <= r) Lsh[r * 65 + c] = A[(size_t)r * Nn + c];
    }
    __syncthreads();

    int tq = tid & 63, trow = tid >> 6;
    for (int c = 0; c < 64; c++) {
        if (tid < 64) colbuf[tid] = Lsh[tid * 65 + c];
        __syncthreads();
        float dv  = sqrtf(colbuf[c]);
        float inv = 1.0f / dv;
        float i2  = inv * inv;
        if (tid < 64) {
            if (tid > c)       Lsh[tid * 65 + c] = colbuf[tid] * inv;
            else if (tid == c) Lsh[c * 65 + c]   = dv;
        }
        if (tq > c) {
            float xq = colbuf[tq] * i2;
            for (int rr = c + 1 + trow; rr < 64; rr += 4)
                Lsh[rr * 65 + tq] -= colbuf[rr] * xq;
        }
        __syncthreads();
    }

    for (int idx = tid; idx < 64 * 64; idx += 256) {
        int r = idx >> 6, c = idx & 63;
        if (c <= r) A[(size_t)r * Nn + c] = Lsh[r * 65 + c];
    }

    if (tid < 64) colbuf[tid] = 1.0f / Lsh[tid * 65 + tid];
    __syncthreads();

    if (tid < 64) {
        int c = tid;
        float x[64];
        x[c] = colbuf[c];
        for (int jj = c + 1; jj < 64; jj++) {
            float s0 = 0.f, s1 = 0.f, s2 = 0.f, s3 = 0.f;
            int k = c;
            for (; k + 3 < jj; k += 4) {
                s0 += Lsh[jj * 65 + k + 0] * x[k + 0];
                s1 += Lsh[jj * 65 + k + 1] * x[k + 1];
                s2 += Lsh[jj * 65 + k + 2] * x[k + 2];
                s3 += Lsh[jj * 65 + k + 3] * x[k + 3];
            }
            for (; k < jj; k++) s0 += Lsh[jj * 65 + k] * x[k];
            x[jj] = -((s0 + s1) + (s2 + s3)) * colbuf[jj];
        }
        for (int jj = 0; jj < 64; jj++)
            g_inv[jj * 64 + c] = (jj >= c) ? x[jj] : 0.f;
    }
    __syncthreads();
}

// Panel solve tile: X = B * invL^T for 64 rows at row0 (in place), step j.
// 256 threads, 2x8 micro-tile.
__device__ void trsm64_tile(float* __restrict__ L, int j, int M, int row0,
                            float* __restrict__ sbuf) {
    float (*As)[68] = (float(*)[68])sbuf;
    float (*Bs)[68] = (float(*)[68])(sbuf + 16 * 68);
    float* B = L + (size_t)(j + 64) * Nn + j;
    int tid = threadIdx.x;
    float acc[2][8];
#pragma unroll
    for (int u = 0; u < 2; u++)
#pragma unroll
        for (int v = 0; v < 8; v++) acc[u][v] = 0.f;

    int ty = tid >> 3, tx = tid & 7;       // ty 0..31, tx 0..7
    int rr = ty * 2, cc = tx * 8;
    int li  = tid >> 2;                    // 0..63
    int lk4 = (tid & 3) << 2;

    for (int kk = 0; kk < 64; kk += 16) {
        float4 av = make_float4(0.f, 0.f, 0.f, 0.f);
        if (row0 + li < M)
            av = *(const float4*)(B + (size_t)(row0 + li) * Nn + kk + lk4);
        float4 bv = *(const float4*)(g_inv + li * 64 + kk + lk4);
        __syncthreads();
        As[lk4 + 0][li] = av.x; As[lk4 + 1][li] = av.y;
        As[lk4 + 2][li] = av.z; As[lk4 + 3][li] = av.w;
        Bs[lk4 + 0][li] = bv.x; Bs[lk4 + 1][li] = bv.y;
        Bs[lk4 + 2][li] = bv.z; Bs[lk4 + 3][li] = bv.w;
        __syncthreads();
#pragma unroll
        for (int k = 0; k < 16; k++) {
            float a0 = As[k][rr], a1 = As[k][rr + 1];
            float bq[8];
            *(float4*)&bq[0] = *(const float4*)&Bs[k][cc];
            *(float4*)&bq[4] = *(const float4*)&Bs[k][cc + 4];
#pragma unroll
            for (int v = 0; v < 8; v++) {
                acc[0][v] += a0 * bq[v];
                acc[1][v] += a1 * bq[v];
            }
        }
    }
    __syncthreads();
#pragma unroll
    for (int u = 0; u < 2; u++) {
        int gr = row0 + rr + u;
        if (gr < M) {
            float* bp = B + (size_t)gr * Nn + cc;
            float4 c0, c1;
            c0.x = acc[u][0]; c0.y = acc[u][1]; c0.z = acc[u][2]; c0.w = acc[u][3];
            c1.x = acc[u][4]; c1.y = acc[u][5]; c1.z = acc[u][6]; c1.w = acc[u][7];
            *(float4*)bp = c0;
            *(float4*)(bp + 4) = c1;
        }
    }
}

// Trailing-update tile: C(128x128 at by,bx) -= P*P^T. Register-prefetch double buffered.
__device__ void syrk_tile(float* __restrict__ L, int j, int M, int bx, int by,
                          float* __restrict__ sbuf) {
    float (*As)[132] = (float(*)[132])sbuf;
    float (*Bs)[132] = (float(*)[132])(sbuf + 16 * 132);
    const float* P = L + (size_t)(j + 64) * Nn + j;
    float* C       = L + (size_t)(j + 64) * Nn + (j + 64);
    int row0 = by * 128, col0 = bx * 128;
    int tid = threadIdx.x;
    float acc[8][8];
#pragma unroll
    for (int u = 0; u < 8; u++)
#pragma unroll
        for (int v = 0; v < 8; v++) acc[u][v] = 0.f;

    int ty = tid >> 4, tx = tid & 15;
    int rr = ty * 8, cc = tx * 8;

    int li[2], lk4[2];
#pragma unroll
    for (int rep = 0; rep < 2; rep++) {
        int f4 = tid + rep * 256;
        li[rep]  = f4 >> 2;
        lk4[rep] = (f4 & 3) << 2;
    }

    float4 pa[2], pb[2];
#pragma unroll
    for (int rep = 0; rep < 2; rep++) {
        pa[rep] = make_float4(0.f, 0.f, 0.f, 0.f);
        pb[rep] = make_float4(0.f, 0.f, 0.f, 0.f);
        if (row0 + li[rep] < M)
            pa[rep] = *(const float4*)(P + (size_t)(row0 + li[rep]) * Nn + lk4[rep]);
        if (col0 + li[rep] < M)
            pb[rep] = *(const float4*)(P + (size_t)(col0 + li[rep]) * Nn + lk4[rep]);
    }

    for (int kk = 0; kk < 64; kk += 16) {
        __syncthreads();
#pragma unroll
        for (int rep = 0; rep < 2; rep++) {
            As[lk4[rep] + 0][li[rep]] = pa[rep].x;
            As[lk4[rep] + 1][li[rep]] = pa[rep].y;
            As[lk4[rep] + 2][li[rep]] = pa[rep].z;
            As[lk4[rep] + 3][li[rep]] = pa[rep].w;
            Bs[lk4[rep] + 0][li[rep]] = pb[rep].x;
            Bs[lk4[rep] + 1][li[rep]] = pb[rep].y;
            Bs[lk4[rep] + 2][li[rep]] = pb[rep].z;
            Bs[lk4[rep] + 3][li[rep]] = pb[rep].w;
        }
        __syncthreads();
        if (kk < 48) {
            int nk = kk + 16;
#pragma unroll
            for (int rep = 0; rep < 2; rep++) {
                pa[rep] = make_float4(0.f, 0.f, 0.f, 0.f);
                pb[rep] = make_float4(0.f, 0.f, 0.f, 0.f);
                if (row0 + li[rep] < M)
                    pa[rep] = *(const float4*)(P + (size_t)(row0 + li[rep]) * Nn + nk + lk4[rep]);
                if (col0 + li[rep] < M)
                    pb[rep] = *(const float4*)(P + (size_t)(col0 + li[rep]) * Nn + nk + lk4[rep]);
            }
        }
#pragma unroll
        for (int k = 0; k < 16; k++) {
            float a[8], bq[8];
            *(float4*)&a[0]  = *(const float4*)&As[k][rr];
            *(float4*)&a[4]  = *(const float4*)&As[k][rr + 4];
            *(float4*)&bq[0] = *(const float4*)&Bs[k][cc];
            *(float4*)&bq[4] = *(const float4*)&Bs[k][cc + 4];
#pragma unroll
            for (int u = 0; u < 8; u++)
#pragma unroll
                for (int v = 0; v < 8; v++) acc[u][v] += a[u] * bq[v];
        }
    }
    __syncthreads();

    if (by > bx) {
#pragma unroll
        for (int u = 0; u < 8; u++) {
            int gr = row0 + rr + u;
            if (gr < M) {
                float* cp = C + (size_t)gr * Nn + col0 + cc;
                float4 c0 = *(float4*)cp;
                float4 c1 = *(float4*)(cp + 4);
                c0.x -= acc[u][0]; c0.y -= acc[u][1]; c0.z -= acc[u][2]; c0.w -= acc[u][3];
                c1.x -= acc[u][4]; c1.y -= acc[u][5]; c1.z -= acc[u][6]; c1.w -= acc[u][7];
                *(float4*)cp = c0;
                *(float4*)(cp + 4) = c1;
            }
        }
    } else {
#pragma unroll
        for (int u = 0; u < 8; u++) {
            int gr = row0 + rr + u;
            if (gr < M) {
#pragma unroll
                for (int v = 0; v < 8; v++) {
                    int gc = col0 + cc + v;
                    if (gc <= gr) C[(size_t)gr * Nn + gc] -= acc[u][v];
                }
            }
        }
    }
}

// map s (0-based) to lower-triangle tile (bx <= by): s = by(by+1)/2 + bx
__device__ __forceinline__ void tri_xy(int s, int& bx, int& by) {
    int byp = (int)((sqrtf(8.0f * (float)s + 1.0f) - 1.0f) * 0.5f);
    while ((byp + 1) * (byp + 2) / 2 <= s) byp++;
    while (byp * (byp + 1) / 2 > s) byp--;
    by = byp;
    bx = s - ((byp * (byp + 1)) >> 1);
}

// ================= THE WHOLE PROBLEM IN ONE PERSISTENT KERNEL =================
__global__ __launch_bounds__(256, 2) void fused_all(
    const float* __restrict__ us, const float* __restrict__ ut,
    const float* __restrict__ kf, const float* __restrict__ thrp,
    const float* __restrict__ iou, const float* __restrict__ W,
    const float* __restrict__ bb,
    float* __restrict__ Mp_out, float* __restrict__ flag_out,
    float* __restrict__ L)
{
    __shared__ float sbuf[4224];
    int bid = blockIdx.x, G = gridDim.x, tid = threadIdx.x;
    int warp = tid >> 5, lane = tid & 31;

    // ---- P0: transpose ----
    for (int idx = bid * 256 + tid; idx < NSd * Dd; idx += G * 256) {
        int i = idx >> 9, d = idx & 511;
        g_e1[idx] = us[d * NSd + i];
        g_e2[idx] = ut[d * NSd + i];
    }
    grid_sync();

    // ---- P1: Mp0 = e1 e2^T + iou ----
    for (int i = bid; i < NSd; i += G) {
        const float* a = g_e1 + i * Dd;
        for (int jj = warp; jj < NSd; jj += 8) {
            const float* bptr = g_e2 + jj * Dd;
            float s = 0.f;
#pragma unroll 4
            for (int d = lane; d < Dd; d += 32) s += a[d] * bptr[d];
            s = warp_sum(s);
            if (lane == 0) g_Mp0[i * NSd + jj] = s + iou[i * NSd + jj];
        }
    }
    grid_sync();

    // ---- P2: m1 = Mp0 e2, m2 = Mp0^T e1 ----
    for (int t = bid; t < 2 * NSd; t += G) {
        int which = t >= NSd;
        int r = t - which * NSd;
        if (tid < NSd) sbuf[tid] = which ? g_Mp0[tid * NSd + r] : g_Mp0[r * NSd + tid];
        __syncthreads();
        const float* E = which ? g_e1 : g_e2;
        float* outp    = which ? g_m2 : g_m1;
        for (int d = tid; d < Dd; d += 256) {
            float acc = 0.f;
#pragma unroll 8
            for (int u = 0; u < NSd; u++) acc += sbuf[u] * E[u * Dd + d];
            outp[r * Dd + d] = acc;
        }
        __syncthreads();
    }
    grid_sync();

    // ---- P3: lam = ||e||/||m||; x = e + lam*m ----
    for (int t = bid; t < 2 * NSd; t += G) {
        int which = t >= NSd;
        int r = t - which * NSd;
        const float* e = (which ? g_e2 : g_e1) + r * Dd;
        const float* m = (which ? g_m2 : g_m1) + r * Dd;
        float* x       = (which ? g_x2 : g_x1) + r * Dd;
        float se = 0.f, sm = 0.f;
        for (int d = tid; d < Dd; d += 256) {
            float ev = e[d], mv = m[d];
            se += ev * ev; sm += mv * mv;
        }
        se = warp_sum(se); sm = warp_sum(sm);
        if (lane == 0) { sbuf[warp] = se; sbuf[8 + warp] = sm; }
        __syncthreads();
        if (tid == 0) {
            float SE = 0.f, SM = 0.f;
            for (int u = 0; u < 8; u++) { SE += sbuf[u]; SM += sbuf[8 + u]; }
            sbuf[16] = sqrtf(SE) / sqrtf(SM);
        }
        __syncthreads();
        float lam = sbuf[16];
        for (int d = tid; d < Dd; d += 256) x[d] = e[d] + lam * m[d];
        __syncthreads();
    }
    grid_sync();

    // ---- P4: y = relu(x W^T + b) ----
    for (int t = bid; t < 2 * NSd; t += G) {
        int which = t >= NSd;
        int r = t - which * NSd;
        const float* X = (which ? g_x2 : g_x1) + r * Dd;
        float* Y       = (which ? g_y2 : g_y1) + r * Dd;
        for (int d = tid; d < Dd; d += 256) sbuf[d] = X[d];
        __syncthreads();
        for (int o = warp; o < Dd; o += 8) {
            const float* wr = W + o * Dd;
            float s = 0.f;
#pragma unroll 4
            for (int d = lane; d < Dd; d += 32) s += sbuf[d] * wr[d];
            s = warp_sum(s);
            if (lane == 0) Y[o] = fmaxf(s + bb[o], 0.f);
        }
        __syncthreads();
    }
    grid_sync();

    // ---- P5: row l2 normalize ----
    for (int t = bid; t < 2 * NSd; t += G) {
        int which = t >= NSd;
        int r = t - which * NSd;
        float* y = (which ? g_y2 : g_y1) + r * Dd;
        float s = 0.f;
        for (int d = tid; d < Dd; d += 256) { float v = y[d]; s += v * v; }
        s = warp_sum(s);
        if (lane == 0) sbuf[warp] = s;
        __syncthreads();
        if (tid == 0) {
            float S = 0.f;
            for (int u = 0; u < 8; u++) S += sbuf[u];
            sbuf[8] = 1.0f / fmaxf(sqrtf(S), 1e-12f);
        }
        __syncthreads();
        float inv = sbuf[8];
        for (int d = tid; d < Dd; d += 256) y[d] *= inv;
        __syncthreads();
    }
    grid_sync();

    // ---- P6: Mp, thr_flag, v ----
    {
        float th = thrp[0];
        for (int i = bid; i < NSd; i += G) {
            const float* a = g_y1 + i * Dd;
            for (int jj = warp; jj < NSd; jj += 8) {
                const float* bptr = g_y2 + jj * Dd;
                float s = 0.f;
#pragma unroll 4
                for (int d = lane; d < Dd; d += 32) s += a[d] * bptr[d];
                s = warp_sum(s);
                if (lane == 0) {
                    Mp_out[i * NSd + jj] = s;
                    g_v[jj * NSd + i] = s;
                    float fl = (kf[i * NSd + jj] == -1.0f || iou[i * NSd + jj] == 0.0f || s < th) ? 1.0f : 0.0f;
                    flag_out[i * NSd + jj] = fl;
                }
            }
        }
    }
    grid_sync();

    // ---- P7: build A into L ----
    for (int p = bid; p < Nn; p += G) {
        int s1 = p % NSd, t1 = p / NSd;
        float vp = g_v[p];
        float* row = L + (size_t)p * Nn;
        for (int q = tid; q < Nn; q += 256) {
            float val = 0.f;
            if (q == p) val = 6241.0f;
            else if (q < p) {
                int s2 = q % NSd, t2 = q / NSd;
                if (s1 != s2 && t1 != t2) val = -0.5f * (vp + g_v[q]);
            }
            row[q] = val;
        }
    }
    grid_sync();

    // ---- P8: Cholesky (R7-simple schedule: 2 phases/step, fused fact64) ----
    if (bid == 0) fact64(L, sbuf);
    grid_sync();

    for (int j = 0; j + 64 < Nn; j += 64) {
        int M  = Nn - j - 64;
        int nt64 = (M + 63) >> 6;                 // 64-row trsm tiles (<=99 => one wave)

        for (int t = bid; t < nt64; t += G)
            trsm64_tile(L, j, M, t << 6, sbuf);
        grid_sync();

        int nt  = (M + 127) >> 7;
        int ntS = nt * (nt + 1) / 2;
        if (bid == 0) {
            syrk_tile(L, j, M, 0, 0, sbuf);
            __syncthreads();
            fact64(L + (size_t)(j + 64) * Nn + (j + 64), sbuf);
        } else {
            for (int s = bid; s < ntS; s += G - 1) {
                int bx, by;
                tri_xy(s, bx, by);
                syrk_tile(L, j, M, bx, by, sbuf);
            }
        }
        grid_sync();
    }
}

// ---------------- launch ----------------
extern "C" void kernel_launch(void* const* d_in, const int* in_sizes, int n_in,
                              void* d_out, int out_size) {
    (void)in_sizes; (void)n_in; (void)out_size;
    const float* U_src = (const float*)d_in[0];
    const float* U_tgt = (const float*)d_in[1];
    const float* kf    = (const float*)d_in[2];
    const float* thrp  = (const float*)d_in[3];
    const float* iou   = (const float*)d_in[4];
    const float* W     = (const float*)d_in[5];
    const float* b     = (const float*)d_in[6];

    float* out      = (float*)d_out;
    float* Mp_out   = out;                       // [80*80]
    float* Lm       = out + NSd * NSd;           // [6400*6400]
    float* flag_out = out + NSd * NSd + Nn * Nn; // [80*80]

    fused_all<<<GPERS, 256>>>(U_src, U_tgt, kf, thrp, iou, W, b,
                              Mp_out, flag_out, Lm);
}

// round 15
// speedup vs baseline: 1.2040x; 1.0594x over previous
#include <cuda_runtime.h>
#include <math.h>

// Problem constants: NS = NT = 80, D = 512, N = 6400, kdiag = 79*79 = 6241.
#define NSd   80
#define Dd    512
#define Nn    6400
#define GPERS 148   // persistent grid; launch_bounds(256,2) guarantees co-residency

typedef unsigned long long u64t;

// Packed fp32x2 FMA (Blackwell): one fma-pipe issue = 2 IEEE fp32 FMAs.
__device__ __forceinline__ u64t ffma2(u64t a, u64t b, u64t c) {
    u64t d;
    asm("fma.rn.f32x2 %0, %1, %2, %3;" : "=l"(d) : "l"(a), "l"(b), "l"(c));
    return d;
}
__device__ __forceinline__ u64t pack2(float x) {
    u64t d;
    asm("mov.b64 %0, {%1, %1};" : "=l"(d) : "f"(x));
    return d;
}

// ---------------- device scratch (no allocation allowed) ----------------
__device__ float g_e1[NSd * Dd];
__device__ float g_e2[NSd * Dd];
__device__ float g_m1[NSd * Dd];
__device__ float g_m2[NSd * Dd];
__device__ float g_x1[NSd * Dd];
__device__ float g_x2[NSd * Dd];
__device__ float g_y1[NSd * Dd];
__device__ float g_y2[NSd * Dd];
__device__ float g_Mp0[NSd * NSd];
__device__ float g_v[Nn];             // v[p] = Mp[p%80, p/80]
__device__ float g_inv[64 * 64];      // invL of current diag block
__device__ int   g_cnt = 0;           // grid barrier arrival counter (self-restoring)
__device__ int   g_gen = 0;           // grid barrier generation (monotonic; compared relatively)

__device__ __forceinline__ float warp_sum(float s) {
#pragma unroll
    for (int o = 16; o > 0; o >>= 1) s += __shfl_xor_sync(0xffffffffu, s, o);
    return s;
}

__device__ __forceinline__ void grid_sync() {
    __threadfence();
    __syncthreads();
    if (threadIdx.x == 0) {
        int gen = atomicAdd(&g_gen, 0);
        if (atomicAdd(&g_cnt, 1) == (int)gridDim.x - 1) {
            g_cnt = 0;
            __threadfence();
            atomicExch(&g_gen, gen + 1);
        } else {
            while (atomicAdd(&g_gen, 0) == gen) { }
        }
    }
    __syncthreads();
}

// ---------------- Cholesky building blocks ----------------

// Factor 64x64 block at A (ld = Nn) in place (lower); write invL into g_inv.
__device__ void fact64(float* __restrict__ A, float* __restrict__ sbuf) {
    float* Lsh    = sbuf;            // 64*65
    float* colbuf = sbuf + 64 * 65;  // 64
    int tid = threadIdx.x;

    for (int idx = tid; idx < 64 * 64; idx += 256) {
        int r = idx >> 6, c = idx & 63;
        if (c <= r) Lsh[r * 65 + c] = A[(size_t)r * Nn + c];
    }
    __syncthreads();

    int tq = tid & 63, trow = tid >> 6;
    for (int c = 0; c < 64; c++) {
        if (tid < 64) colbuf[tid] = Lsh[tid * 65 + c];
        __syncthreads();
        float dv  = sqrtf(colbuf[c]);
        float inv = 1.0f / dv;
        float i2  = inv * inv;
        if (tid < 64) {
            if (tid > c)       Lsh[tid * 65 + c] = colbuf[tid] * inv;
            else if (tid == c) Lsh[c * 65 + c]   = dv;
        }
        if (tq > c) {
            float xq = colbuf[tq] * i2;
            for (int rr = c + 1 + trow; rr < 64; rr += 4)
                Lsh[rr * 65 + tq] -= colbuf[rr] * xq;
        }
        __syncthreads();
    }

    for (int idx = tid; idx < 64 * 64; idx += 256) {
        int r = idx >> 6, c = idx & 63;
        if (c <= r) A[(size_t)r * Nn + c] = Lsh[r * 65 + c];
    }

    if (tid < 64) colbuf[tid] = 1.0f / Lsh[tid * 65 + tid];
    __syncthreads();

    if (tid < 64) {
        int c = tid;
        float x[64];
        x[c] = colbuf[c];
        for (int jj = c + 1; jj < 64; jj++) {
            float s0 = 0.f, s1 = 0.f, s2 = 0.f, s3 = 0.f;
            int k = c;
            for (; k + 3 < jj; k += 4) {
                s0 += Lsh[jj * 65 + k + 0] * x[k + 0];
                s1 += Lsh[jj * 65 + k + 1] * x[k + 1];
                s2 += Lsh[jj * 65 + k + 2] * x[k + 2];
                s3 += Lsh[jj * 65 + k + 3] * x[k + 3];
            }
            for (; k < jj; k++) s0 += Lsh[jj * 65 + k] * x[k];
            x[jj] = -((s0 + s1) + (s2 + s3)) * colbuf[jj];
        }
        for (int jj = 0; jj < 64; jj++)
            g_inv[jj * 64 + c] = (jj >= c) ? x[jj] : 0.f;
    }
    __syncthreads();
}

// Panel solve tile: X = B * invL^T for 64 rows at row0 (in place), step j.
// 256 threads, 2x8 micro-tile, packed f32x2 FMA.
__device__ void trsm64_tile(float* __restrict__ L, int j, int M, int row0,
                            float* __restrict__ sbuf) {
    float (*As)[68] = (float(*)[68])sbuf;
    float (*Bs)[68] = (float(*)[68])(sbuf + 16 * 68);
    float* B = L + (size_t)(j + 64) * Nn + j;
    int tid = threadIdx.x;

    u64t acc2[2][4];
#pragma unroll
    for (int u = 0; u < 2; u++)
#pragma unroll
        for (int v = 0; v < 4; v++) acc2[u][v] = 0ull;

    int ty = tid >> 3, tx = tid & 7;       // ty 0..31, tx 0..7
    int rr = ty * 2, cc = tx * 8;
    int li  = tid >> 2;                    // 0..63
    int lk4 = (tid & 3) << 2;

    for (int kk = 0; kk < 64; kk += 16) {
        float4 av = make_float4(0.f, 0.f, 0.f, 0.f);
        if (row0 + li < M)
            av = *(const float4*)(B + (size_t)(row0 + li) * Nn + kk + lk4);
        float4 bv = *(const float4*)(g_inv + li * 64 + kk + lk4);
        __syncthreads();
        As[lk4 + 0][li] = av.x; As[lk4 + 1][li] = av.y;
        As[lk4 + 2][li] = av.z; As[lk4 + 3][li] = av.w;
        Bs[lk4 + 0][li] = bv.x; Bs[lk4 + 1][li] = bv.y;
        Bs[lk4 + 2][li] = bv.z; Bs[lk4 + 3][li] = bv.w;
        __syncthreads();
#pragma unroll
        for (int k = 0; k < 16; k++) {
            u64t a0 = pack2(As[k][rr]);
            u64t a1 = pack2(As[k][rr + 1]);
            union { float4 f4[2]; u64t u2[4]; } bq;
            bq.f4[0] = *(const float4*)&Bs[k][cc];
            bq.f4[1] = *(const float4*)&Bs[k][cc + 4];
#pragma unroll
            for (int v = 0; v < 4; v++) {
                acc2[0][v] = ffma2(a0, bq.u2[v], acc2[0][v]);
                acc2[1][v] = ffma2(a1, bq.u2[v], acc2[1][v]);
            }
        }
    }
    __syncthreads();
#pragma unroll
    for (int u = 0; u < 2; u++) {
        int gr = row0 + rr + u;
        if (gr < M) {
            union { u64t u2[4]; float4 f4[2]; } r;
#pragma unroll
            for (int v = 0; v < 4; v++) r.u2[v] = acc2[u][v];
            float* bp = B + (size_t)gr * Nn + cc;
            *(float4*)bp       = r.f4[0];
            *(float4*)(bp + 4) = r.f4[1];
        }
    }
}

// Trailing-update tile: C(128x128 at by,bx) -= P*P^T.
// Register-prefetch double buffered, packed f32x2 FMA.
__device__ void syrk_tile(float* __restrict__ L, int j, int M, int bx, int by,
                          float* __restrict__ sbuf) {
    float (*As)[132] = (float(*)[132])sbuf;
    float (*Bs)[132] = (float(*)[132])(sbuf + 16 * 132);
    const float* P = L + (size_t)(j + 64) * Nn + j;
    float* C       = L + (size_t)(j + 64) * Nn + (j + 64);
    int row0 = by * 128, col0 = bx * 128;
    int tid = threadIdx.x;

    u64t acc2[8][4];
#pragma unroll
    for (int u = 0; u < 8; u++)
#pragma unroll
        for (int v = 0; v < 4; v++) acc2[u][v] = 0ull;

    int ty = tid >> 4, tx = tid & 15;
    int rr = ty * 8, cc = tx * 8;

    int li[2], lk4[2];
#pragma unroll
    for (int rep = 0; rep < 2; rep++) {
        int f4 = tid + rep * 256;
        li[rep]  = f4 >> 2;
        lk4[rep] = (f4 & 3) << 2;
    }

    float4 pa[2], pb[2];
#pragma unroll
    for (int rep = 0; rep < 2; rep++) {
        pa[rep] = make_float4(0.f, 0.f, 0.f, 0.f);
        pb[rep] = make_float4(0.f, 0.f, 0.f, 0.f);
        if (row0 + li[rep] < M)
            pa[rep] = *(const float4*)(P + (size_t)(row0 + li[rep]) * Nn + lk4[rep]);
        if (col0 + li[rep] < M)
            pb[rep] = *(const float4*)(P + (size_t)(col0 + li[rep]) * Nn + lk4[rep]);
    }

    for (int kk = 0; kk < 64; kk += 16) {
        __syncthreads();
#pragma unroll
        for (int rep = 0; rep < 2; rep++) {
            As[lk4[rep] + 0][li[rep]] = pa[rep].x;
            As[lk4[rep] + 1][li[rep]] = pa[rep].y;
            As[lk4[rep] + 2][li[rep]] = pa[rep].z;
            As[lk4[rep] + 3][li[rep]] = pa[rep].w;
            Bs[lk4[rep] + 0][li[rep]] = pb[rep].x;
            Bs[lk4[rep] + 1][li[rep]] = pb[rep].y;
            Bs[lk4[rep] + 2][li[rep]] = pb[rep].z;
            Bs[lk4[rep] + 3][li[rep]] = pb[rep].w;
        }
        __syncthreads();
        if (kk < 48) {
            int nk = kk + 16;
#pragma unroll
            for (int rep = 0; rep < 2; rep++) {
                pa[rep] = make_float4(0.f, 0.f, 0.f, 0.f);
                pb[rep] = make_float4(0.f, 0.f, 0.f, 0.f);
                if (row0 + li[rep] < M)
                    pa[rep] = *(const float4*)(P + (size_t)(row0 + li[rep]) * Nn + nk + lk4[rep]);
                if (col0 + li[rep] < M)
                    pb[rep] = *(const float4*)(P + (size_t)(col0 + li[rep]) * Nn + nk + lk4[rep]);
            }
        }
#pragma unroll
        for (int k = 0; k < 16; k++) {
            float a[8];
            *(float4*)&a[0]  = *(const float4*)&As[k][rr];
            *(float4*)&a[4]  = *(const float4*)&As[k][rr + 4];
            union { float4 f4[2]; u64t u2[4]; } bq;
            bq.f4[0] = *(const float4*)&Bs[k][cc];
            bq.f4[1] = *(const float4*)&Bs[k][cc + 4];
#pragma unroll
            for (int u = 0; u < 8; u++) {
                u64t au = pack2(a[u]);
#pragma unroll
                for (int v = 0; v < 4; v++)
                    acc2[u][v] = ffma2(au, bq.u2[v], acc2[u][v]);
            }
        }
    }
    __syncthreads();

    if (by > bx) {
#pragma unroll
        for (int u = 0; u < 8; u++) {
            int gr = row0 + rr + u;
            if (gr < M) {
                union { u64t u2[4]; float f[8]; } r;
#pragma unroll
                for (int v = 0; v < 4; v++) r.u2[v] = acc2[u][v];
                float* cp = C + (size_t)gr * Nn + col0 + cc;
                float4 c0 = *(float4*)cp;
                float4 c1 = *(float4*)(cp + 4);
                c0.x -= r.f[0]; c0.y -= r.f[1]; c0.z -= r.f[2]; c0.w -= r.f[3];
                c1.x -= r.f[4]; c1.y -= r.f[5]; c1.z -= r.f[6]; c1.w -= r.f[7];
                *(float4*)cp = c0;
                *(float4*)(cp + 4) = c1;
            }
        }
    } else {
#pragma unroll
        for (int u = 0; u < 8; u++) {
            int gr = row0 + rr + u;
            if (gr < M) {
                union { u64t u2[4]; float f[8]; } r;
#pragma unroll
                for (int v = 0; v < 4; v++) r.u2[v] = acc2[u][v];
#pragma unroll
                for (int v = 0; v < 8; v++) {
                    int gc = col0 + cc + v;
                    if (gc <= gr) C[(size_t)gr * Nn + gc] -= r.f[v];
                }
            }
        }
    }
}

// map s (0-based) to lower-triangle tile (bx <= by): s = by(by+1)/2 + bx
__device__ __forceinline__ void tri_xy(int s, int& bx, int& by) {
    int byp = (int)((sqrtf(8.0f * (float)s + 1.0f) - 1.0f) * 0.5f);
    while ((byp + 1) * (byp + 2) / 2 <= s) byp++;
    while (byp * (byp + 1) / 2 > s) byp--;
    by = byp;
    bx = s - ((byp * (byp + 1)) >> 1);
}

// ================= THE WHOLE PROBLEM IN ONE PERSISTENT KERNEL =================
__global__ __launch_bounds__(256, 2) void fused_all(
    const float* __restrict__ us, const float* __restrict__ ut,
    const float* __restrict__ kf, const float* __restrict__ thrp,
    const float* __restrict__ iou, const float* __restrict__ W,
    const float* __restrict__ bb,
    float* __restrict__ Mp_out, float* __restrict__ flag_out,
    float* __restrict__ L)
{
    __shared__ float sbuf[4224];
    int bid = blockIdx.x, G = gridDim.x, tid = threadIdx.x;
    int warp = tid >> 5, lane = tid & 31;

    // ---- P0: transpose ----
    for (int idx = bid * 256 + tid; idx < NSd * Dd; idx += G * 256) {
        int i = idx >> 9, d = idx & 511;
        g_e1[idx] = us[d * NSd + i];
        g_e2[idx] = ut[d * NSd + i];
    }
    grid_sync();

    // ---- P1: Mp0 = e1 e2^T + iou ----
    for (int i = bid; i < NSd; i += G) {
        const float* a = g_e1 + i * Dd;
        for (int jj = warp; jj < NSd; jj += 8) {
            const float* bptr = g_e2 + jj * Dd;
            float s = 0.f;
#pragma unroll 4
            for (int d = lane; d < Dd; d += 32) s += a[d] * bptr[d];
            s = warp_sum(s);
            if (lane == 0) g_Mp0[i * NSd + jj] = s + iou[i * NSd + jj];
        }
    }
    grid_sync();

    // ---- P2: m1 = Mp0 e2, m2 = Mp0^T e1 ----
    for (int t = bid; t < 2 * NSd; t += G) {
        int which = t >= NSd;
        int r = t - which * NSd;
        if (tid < NSd) sbuf[tid] = which ? g_Mp0[tid * NSd + r] : g_Mp0[r * NSd + tid];
        __syncthreads();
        const float* E = which ? g_e1 : g_e2;
        float* outp    = which ? g_m2 : g_m1;
        for (int d = tid; d < Dd; d += 256) {
            float acc = 0.f;
#pragma unroll 8
            for (int u = 0; u < NSd; u++) acc += sbuf[u] * E[u * Dd + d];
            outp[r * Dd + d] = acc;
        }
        __syncthreads();
    }
    grid_sync();

    // ---- P3: lam = ||e||/||m||; x = e + lam*m ----
    for (int t = bid; t < 2 * NSd; t += G) {
        int which = t >= NSd;
        int r = t - which * NSd;
        const float* e = (which ? g_e2 : g_e1) + r * Dd;
        const float* m = (which ? g_m2 : g_m1) + r * Dd;
        float* x       = (which ? g_x2 : g_x1) + r * Dd;
        float se = 0.f, sm = 0.f;
        for (int d = tid; d < Dd; d += 256) {
            float ev = e[d], mv = m[d];
            se += ev * ev; sm += mv * mv;
        }
        se = warp_sum(se); sm = warp_sum(sm);
        if (lane == 0) { sbuf[warp] = se; sbuf[8 + warp] = sm; }
        __syncthreads();
        if (tid == 0) {
            float SE = 0.f, SM = 0.f;
            for (int u = 0; u < 8; u++) { SE += sbuf[u]; SM += sbuf[8 + u]; }
            sbuf[16] = sqrtf(SE) / sqrtf(SM);
        }
        __syncthreads();
        float lam = sbuf[16];
        for (int d = tid; d < Dd; d += 256) x[d] = e[d] + lam * m[d];
        __syncthreads();
    }
    grid_sync();

    // ---- P4: y = relu(x W^T + b) ----
    for (int t = bid; t < 2 * NSd; t += G) {
        int which = t >= NSd;
        int r = t - which * NSd;
        const float* X = (which ? g_x2 : g_x1) + r * Dd;
        float* Y       = (which ? g_y2 : g_y1) + r * Dd;
        for (int d = tid; d < Dd; d += 256) sbuf[d] = X[d];
        __syncthreads();
        for (int o = warp; o < Dd; o += 8) {
            const float* wr = W + o * Dd;
            float s = 0.f;
#pragma unroll 4
            for (int d = lane; d < Dd; d += 32) s += sbuf[d] * wr[d];
            s = warp_sum(s);
            if (lane == 0) Y[o] = fmaxf(s + bb[o], 0.f);
        }
        __syncthreads();
    }
    grid_sync();

    // ---- P5: row l2 normalize ----
    for (int t = bid; t < 2 * NSd; t += G) {
        int which = t >= NSd;
        int r = t - which * NSd;
        float* y = (which ? g_y2 : g_y1) + r * Dd;
        float s = 0.f;
        for (int d = tid; d < Dd; d += 256) { float v = y[d]; s += v * v; }
        s = warp_sum(s);
        if (lane == 0) sbuf[warp] = s;
        __syncthreads();
        if (tid == 0) {
            float S = 0.f;
            for (int u = 0; u < 8; u++) S += sbuf[u];
            sbuf[8] = 1.0f / fmaxf(sqrtf(S), 1e-12f);
        }
        __syncthreads();
        float inv = sbuf[8];
        for (int d = tid; d < Dd; d += 256) y[d] *= inv;
        __syncthreads();
    }
    grid_sync();

    // ---- P6: Mp, thr_flag, v ----
    {
        float th = thrp[0];
        for (int i = bid; i < NSd; i += G) {
            const float* a = g_y1 + i * Dd;
            for (int jj = warp; jj < NSd; jj += 8) {
                const float* bptr = g_y2 + jj * Dd;
                float s = 0.f;
#pragma unroll 4
                for (int d = lane; d < Dd; d += 32) s += a[d] * bptr[d];
                s = warp_sum(s);
                if (lane == 0) {
                    Mp_out[i * NSd + jj] = s;
                    g_v[jj * NSd + i] = s;
                    float fl = (kf[i * NSd + jj] == -1.0f || iou[i * NSd + jj] == 0.0f || s < th) ? 1.0f : 0.0f;
                    flag_out[i * NSd + jj] = fl;
                }
            }
        }
    }
    grid_sync();

    // ---- P7: build A into L ----
    for (int p = bid; p < Nn; p += G) {
        int s1 = p % NSd, t1 = p / NSd;
        float vp = g_v[p];
        float* row = L + (size_t)p * Nn;
        for (int q = tid; q < Nn; q += 256) {
            float val = 0.f;
            if (q == p) val = 6241.0f;
            else if (q < p) {
                int s2 = q % NSd, t2 = q / NSd;
                if (s1 != s2 && t1 != t2) val = -0.5f * (vp + g_v[q]);
            }
            row[q] = val;
        }
    }
    grid_sync();

    // ---- P8: Cholesky (simple schedule: 2 phases/step, fused fact64) ----
    if (bid == 0) fact64(L, sbuf);
    grid_sync();

    for (int j = 0; j + 64 < Nn; j += 64) {
        int M  = Nn - j - 64;
        int nt64 = (M + 63) >> 6;                 // 64-row trsm tiles (<=99 => one wave)

        for (int t = bid; t < nt64; t += G)
            trsm64_tile(L, j, M, t << 6, sbuf);
        grid_sync();

        int nt  = (M + 127) >> 7;
        int ntS = nt * (nt + 1) / 2;
        if (bid == 0) {
            syrk_tile(L, j, M, 0, 0, sbuf);
            __syncthreads();
            fact64(L + (size_t)(j + 64) * Nn + (j + 64), sbuf);
        } else {
            for (int s = bid; s < ntS; s += G - 1) {
                int bx, by;
                tri_xy(s, bx, by);
                syrk_tile(L, j, M, bx, by, sbuf);
            }
        }
        grid_sync();
    }
}

// ---------------- launch ----------------
extern "C" void kernel_launch(void* const* d_in, const int* in_sizes, int n_in,
                              void* d_out, int out_size) {
    (void)in_sizes; (void)n_in; (void)out_size;
    const float* U_src = (const float*)d_in[0];
    const float* U_tgt = (const float*)d_in[1];
    const float* kf    = (const float*)d_in[2];
    const float* thrp  = (const float*)d_in[3];
    const float* iou   = (const float*)d_in[4];
    const float* W     = (const float*)d_in[5];
    const float* b     = (const float*)d_in[6];

    float* out      = (float*)d_out;
    float* Mp_out   = out;                       // [80*80]
    float* Lm       = out + NSd * NSd;           // [6400*6400]
    float* flag_out = out + NSd * NSd + Nn * Nn; // [80*80]

    fused_all<<<GPERS, 256>>>(U_src, U_tgt, kf, thrp, iou, W, b,
                              Mp_out, flag_out, Lm);
}